// round 1
// baseline (speedup 1.0000x reference)
#include <cuda_runtime.h>
#include <cuda_bf16.h>
#include <cstdint>

// Flatten 2x2 blocks:
//   out[bc, i*1024 + 4j + 2r + s] = x[bc, 2i+r, 2j+s]
// with x: (B=32, C=3, H=512, W=512) fp32, bc = b*C + c (same linear order
// in and out since both flatten (b, c) identically).
//
// Each thread produces one output float4:
//   out4[bc*65536 + i*256 + j] = { x[2i, 2j], x[2i, 2j+1], x[2i+1, 2j], x[2i+1, 2j+1] }
// via two float2 loads (8B, lane-stride 8B -> fully coalesced) and one
// float4 store (16B, lane-stride 16B -> fully coalesced).

__global__ __launch_bounds__(256)
void flatten2x2_kernel(const float2* __restrict__ x2, float4* __restrict__ out4) {
    // total threads = 32*3 * 256 * 256 = 6,291,456
    unsigned t = blockIdx.x * 256u + threadIdx.x;

    unsigned j  = t & 255u;          // column pair index, 0..255
    unsigned i  = (t >> 8) & 255u;   // row pair index,    0..255
    unsigned bc = t >> 16;           // batch*channel,     0..95

    // x2 is float2-typed: x2[row*256 + j] = (x[row, 2j], x[row, 2j+1])
    const float2* rowbase = x2 + (size_t)bc * 131072u + (size_t)(2u * i) * 256u + j;
    float2 a = __ldg(rowbase);          // row 2i
    float2 b = __ldg(rowbase + 256);    // row 2i+1

    float4 o;
    o.x = a.x; o.y = a.y; o.z = b.x; o.w = b.y;

    out4[(size_t)bc * 65536u + (size_t)i * 256u + j] = o;
}

extern "C" void kernel_launch(void* const* d_in, const int* in_sizes, int n_in,
                              void* d_out, int out_size) {
    const float2* x2 = (const float2*)d_in[0];
    float4* out4 = (float4*)d_out;

    // 32*3*512*512 floats = 6,291,456 float4 outputs
    const unsigned total_threads = 6291456u;
    const unsigned block = 256u;
    const unsigned grid = total_threads / block;  // 24576

    flatten2x2_kernel<<<grid, block>>>(x2, out4);
}